// round 16
// baseline (speedup 1.0000x reference)
#include <cuda_runtime.h>
#include <cstdint>

#define N_TOT 8192
#define DIMS  512
#define NI    8
#define NW    1024          // N_TOT / NI
#define MARGIN 0.3f
#define EPSF   1e-12f

typedef unsigned int u32;
typedef unsigned long long u64;

// ---------------- scratch (static device globals; no allocation) ------------
__device__ float g_sq[N_TOT];
__device__ float g_protos[NW * DIMS];
__device__ float g_psq[NW];
__device__ float g_distap[N_TOT];
__device__ u32   g_minneg[N_TOT];     // float-bits of min neg d2
__device__ u64   g_protomin[N_TOT];   // (d2bits<<32)|class

// ---------------- per-class prep (fp32-exact) + init -------------------------
__global__ void prep_kernel(const float* __restrict__ x, float* __restrict__ out) {
    __shared__ float xs[NI][DIMS + 4];
    __shared__ float dots[NI][NI];
    const int cls = blockIdx.x;
    const int tid = threadIdx.x;
    const float* base = x + (size_t)cls * NI * DIMS;

    if (cls == 0 && tid < 4) out[tid] = 0.f;   // zero output accumulators

    if (tid < NI) {                            // fused init
        g_minneg[cls * NI + tid]   = 0x7f800000u;
        g_protomin[cls * NI + tid] = 0xFFFFFFFFFFFFFFFFull;
    }

    // float4 loads: 1024 float4 segments, 4 per thread
    {
        const float4* src = (const float4*)base;
        #pragma unroll
        for (int i = 0; i < 4; i++) {
            int k4 = tid + i * 256;            // 0..1023
            int r  = k4 >> 7;                  // 0..7
            int c4 = k4 & 127;
            *(float4*)&xs[r][c4 * 4] = src[k4];
        }
    }
    __syncthreads();

    // prototype (psq derived from dots below)
    for (int d = tid; d < DIMS; d += 256) {
        float s = 0.f;
        #pragma unroll
        for (int r = 0; r < NI; r++) s += xs[r][d];
        g_protos[cls * DIMS + d] = s * (1.0f / NI);
    }

    // 8x8 dots: one thread per pair, LDS.128 reads, 4 ILP accumulators
    if (tid < NI * NI) {
        int a = tid >> 3, b = tid & 7;
        const float4* ra = (const float4*)xs[a];
        const float4* rb = (const float4*)xs[b];
        float d0 = 0.f, d1 = 0.f, d2 = 0.f, d3 = 0.f;
        #pragma unroll 8
        for (int k4 = 0; k4 < DIMS / 4; k4++) {
            float4 va = ra[k4], vb = rb[k4];
            d0 = fmaf(va.x, vb.x, d0);
            d1 = fmaf(va.y, vb.y, d1);
            d2 = fmaf(va.z, vb.z, d2);
            d3 = fmaf(va.w, vb.w, d3);
        }
        float dot = (d0 + d1) + (d2 + d3);
        dots[a][b] = dot;
        if (a == b) g_sq[cls * NI + a] = dot;
    }
    __syncthreads();

    if (tid == 0) {
        // ||proto||^2 = (1/64) * sum_{a,b} x_a . x_b
        float s = 0.f;
        #pragma unroll
        for (int a = 0; a < NI; a++)
            #pragma unroll
            for (int b = 0; b < NI; b++) s += dots[a][b];
        g_psq[cls] = s * (1.0f / (NI * NI));
    }
    if (tid < NI) {
        int a = tid;
        float sqa = dots[a][a];
        float m = -1.f;
        #pragma unroll
        for (int b = 0; b < NI; b++) {
            float d2 = sqa + dots[b][b] - 2.f * dots[a][b];
            m = fmaxf(m, sqrtf(fmaxf(d2, EPSF)));
        }
        g_distap[cls * NI + a] = m;
    }
}

// ---------------- mma.sync tf32 helpers --------------------------------------
__device__ __forceinline__ void mma_tf32(float d[4], const u32 a[4], const u32 b[2]) {
    asm volatile(
        "mma.sync.aligned.m16n8k8.row.col.f32.tf32.tf32.f32 "
        "{%0,%1,%2,%3}, {%4,%5,%6,%7}, {%8,%9}, {%0,%1,%2,%3};"
        : "+f"(d[0]), "+f"(d[1]), "+f"(d[2]), "+f"(d[3])
        : "r"(a[0]), "r"(a[1]), "r"(a[2]), "r"(a[3]), "r"(b[0]), "r"(b[1]));
}
__device__ __forceinline__ void cpa16(u32 dst, const float* src) {
    asm volatile("cp.async.ca.shared.global [%0], [%1], 16;" :: "r"(dst), "l"(src));
}
__device__ __forceinline__ void cp_commit() {
    asm volatile("cp.async.commit_group;" ::: "memory");
}

// ---------------- fused tf32 mma GEMM + mining, merged grid ------------------
// CTA tile 128 rows x 256 cols. 8 warps, each 64x64 = 4x8 m16n8k8 frags.
// K chunked by 32 floats, 4-stage cp.async pipeline (221 KB smem),
// wait_group 2 -> 2 chunks always outstanding, 1 barrier per chunk.
// Blocks [0, 1056): wedge tiles of the self-Gram (row+col mining).
// Blocks [1056, 1312): proto GEMM tiles (64 row-blocks x 4 col-blocks).
#define TSTRIDE 36
#define A_ROWS  128
#define B_ROWS  256
#define A_F     (A_ROWS * TSTRIDE)
#define STAGE_F ((A_ROWS + B_ROWS) * TSTRIDE)  // 13824 floats
#define NSTAGE  4
#define NCHUNK  16                        // 512 / 32
#define TRI_BLKS 1056
#define DSMEM   (NSTAGE * STAGE_F * 4)    // 221184 bytes

__global__ __launch_bounds__(256)
void mma_gemm_kernel(const float* __restrict__ A, const float* __restrict__ P) {
    extern __shared__ float dsm[];

    const int tid  = threadIdx.x;
    const int wid  = tid >> 5;
    const int lane = tid & 31;
    const int g    = lane >> 2;
    const int tg   = lane & 3;
    const int rowOff = (wid >> 2) * 64;   // 0 or 64
    const int colOff = (wid & 3) * 64;    // 0,64,128,192

    // ---- decode block -> (mode, rowBase, colBase) ----
    int mode, bxr, byr;
    if ((int)blockIdx.x < TRI_BLKS) {
        mode = 0;
        int t = blockIdx.x;
        int q = (int)((65.0f - sqrtf(4225.0f - 4.0f * (float)t)) * 0.5f);
        if (q < 0) q = 0;
        while (64 * (q + 1) - (q + 1) * q <= t) ++q;
        while (64 * q - q * (q - 1) > t) --q;
        int rem = t - (64 * q - q * (q - 1));
        int cnt = 32 - q;
        int sub = rem >= cnt ? 1 : 0;
        byr = 2 * q + sub;
        bxr = q + (rem - sub * cnt);
    } else {
        mode = 1;
        int p = blockIdx.x - TRI_BLKS;    // 0..255
        byr = p >> 2;
        bxr = p & 3;
    }
    const int rowBase = byr * 128;
    const int colBase = bxr * 256;
    const float* __restrict__ Bp = mode ? P : A;

    auto load_stage = [&](int slot, int c) {
        float* base = dsm + slot * STAGE_F;
        const int k0 = c * 32;
        #pragma unroll
        for (int i = 0; i < 12; i++) {
            int f  = tid + i * 256;              // 0..3071
            int r  = f >> 3;                     // 0..383
            int kc = (f & 7) * 4;
            const float* src;
            float* dstp;
            if (r < A_ROWS) {
                src  = A + (size_t)(rowBase + r) * DIMS + k0 + kc;
                dstp = base + r * TSTRIDE + kc;
            } else {
                src  = Bp + (size_t)(colBase + (r - A_ROWS)) * DIMS + k0 + kc;
                dstp = base + A_F + (r - A_ROWS) * TSTRIDE + kc;
            }
            cpa16((u32)__cvta_generic_to_shared(dstp), src);
        }
        cp_commit();
    };

    float acc[4][8][4];
    #pragma unroll
    for (int mi = 0; mi < 4; mi++)
        #pragma unroll
        for (int nt = 0; nt < 8; nt++)
            #pragma unroll
            for (int q = 0; q < 4; q++) acc[mi][nt][q] = 0.f;

    load_stage(0, 0);
    load_stage(1, 1);
    load_stage(2, 2);

    for (int c = 0; c < NCHUNK; c++) {
        asm volatile("cp.async.wait_group 2;" ::: "memory");
        __syncthreads();
        if (c + 3 < NCHUNK) load_stage((c + 3) % NSTAGE, c + 3);
        else                cp_commit();     // keep group indexing uniform

        const float* Asb = dsm + (c % NSTAGE) * STAGE_F;
        const float* Bsb = Asb + A_F;
        #pragma unroll
        for (int h = 0; h < 4; h++) {
            const int kc = h * 8 + tg;
            u32 afr[4][4];
            #pragma unroll
            for (int mi = 0; mi < 4; mi++) {
                const float* ap = Asb + (rowOff + mi * 16 + g) * TSTRIDE;
                afr[mi][0] = __float_as_uint(ap[kc]);
                afr[mi][1] = __float_as_uint(ap[8 * TSTRIDE + kc]);
                afr[mi][2] = __float_as_uint(ap[kc + 4]);
                afr[mi][3] = __float_as_uint(ap[8 * TSTRIDE + kc + 4]);
            }
            u32 bfr[8][2];
            #pragma unroll
            for (int nt = 0; nt < 8; nt++) {
                const float* bp = Bsb + (colOff + nt * 8 + g) * TSTRIDE;
                bfr[nt][0] = __float_as_uint(bp[kc]);
                bfr[nt][1] = __float_as_uint(bp[kc + 4]);
            }
            #pragma unroll
            for (int mi = 0; mi < 4; mi++)
                #pragma unroll
                for (int nt = 0; nt < 8; nt++)
                    mma_tf32(acc[mi][nt], afr[mi], bfr[nt]);
        }
    }
    asm volatile("cp.async.wait_group 0;" ::: "memory");
    __syncthreads();

    // ---------------- epilogue: mine (arrays aliased into dsm) ----------------
    float* s_sqc  = dsm;                   // 256 f32
    u32*   s_rmin = (u32*)(dsm + 256);     // 128 u32
    u32*   s_cmin = (u32*)(dsm + 384);     // 256 u32
    u64*   s_key  = (u64*)(dsm + 640);     // 128 u64

    const float INF = __int_as_float(0x7f800000);
    s_sqc[tid]  = (mode == 0) ? g_sq[colBase + tid] : g_psq[colBase + tid];
    s_cmin[tid] = 0x7f800000u;
    if (tid < 128) {
        s_rmin[tid] = 0x7f800000u;
        s_key[tid]  = 0xFFFFFFFFFFFFFFFFull;
    }
    __syncthreads();

    const bool straddle = (mode == 0) && ((byr >> 1) == bxr);

    if (mode == 0) {
        float cm[8][2];
        #pragma unroll
        for (int nt = 0; nt < 8; nt++) { cm[nt][0] = INF; cm[nt][1] = INF; }

        #pragma unroll
        for (int mi = 0; mi < 4; mi++) {
            #pragma unroll
            for (int half = 0; half < 2; half++) {
                const int r = rowOff + mi * 16 + g + half * 8;
                const float sqr = g_sq[rowBase + r];
                const int rcls = (rowBase + r) >> 3;
                float rmin = INF;
                #pragma unroll
                for (int nt = 0; nt < 8; nt++) {
                    #pragma unroll
                    for (int cc = 0; cc < 2; cc++) {
                        const int col = colOff + nt * 8 + 2 * tg + cc;
                        float dot = acc[mi][nt][half * 2 + cc];
                        float d2 = fmaxf(sqr + s_sqc[col] - 2.f * dot, 0.f);
                        if (straddle && (((colBase + col) >> 3) == rcls)) d2 = INF;
                        rmin = fminf(rmin, d2);
                        cm[nt][cc] = fminf(cm[nt][cc], d2);
                    }
                }
                atomicMin(&s_rmin[r], __float_as_uint(rmin));
            }
        }
        #pragma unroll
        for (int off = 4; off < 32; off <<= 1)
            #pragma unroll
            for (int nt = 0; nt < 8; nt++) {
                cm[nt][0] = fminf(cm[nt][0], __shfl_xor_sync(0xffffffffu, cm[nt][0], off));
                cm[nt][1] = fminf(cm[nt][1], __shfl_xor_sync(0xffffffffu, cm[nt][1], off));
            }
        if (g == 0) {
            #pragma unroll
            for (int nt = 0; nt < 8; nt++) {
                atomicMin(&s_cmin[colOff + nt * 8 + 2 * tg],     __float_as_uint(cm[nt][0]));
                atomicMin(&s_cmin[colOff + nt * 8 + 2 * tg + 1], __float_as_uint(cm[nt][1]));
            }
        }
        __syncthreads();
        if (tid < 128) atomicMin(&g_minneg[rowBase + tid], s_rmin[tid]);
        atomicMin(&g_minneg[colBase + tid], s_cmin[tid]);
    } else {
        #pragma unroll
        for (int mi = 0; mi < 4; mi++) {
            #pragma unroll
            for (int half = 0; half < 2; half++) {
                const int r = rowOff + mi * 16 + g + half * 8;
                const float sqr = g_sq[rowBase + r];
                u64 kmin = 0xFFFFFFFFFFFFFFFFull;
                #pragma unroll
                for (int nt = 0; nt < 8; nt++) {
                    #pragma unroll
                    for (int cc = 0; cc < 2; cc++) {
                        const int col = colOff + nt * 8 + 2 * tg + cc;
                        float dot = acc[mi][nt][half * 2 + cc];
                        float d2 = fmaxf(sqr + s_sqc[col] - 2.f * dot, 0.f);
                        u64 key = ((u64)__float_as_uint(d2) << 32) | (u32)(colBase + col);
                        kmin = key < kmin ? key : kmin;
                    }
                }
                #pragma unroll
                for (int off = 1; off < 4; off <<= 1) {
                    u64 o = __shfl_xor_sync(0xffffffffu, kmin, off);
                    kmin = o < kmin ? o : kmin;
                }
                if (tg == 0) atomicMin(&s_key[r], kmin);
            }
        }
        __syncthreads();
        if (tid < 128) atomicMin(&g_protomin[rowBase + tid], s_key[tid]);
    }
}

// ---------------- finalize: 32 blocks, atomic accumulate ---------------------
__global__ void finalize_kernel(float* __restrict__ out) {
    __shared__ float red[4][8];
    const int i = blockIdx.x * 256 + threadIdx.x;
    const int tid = threadIdx.x;

    float dap = g_distap[i];
    float dan = sqrtf(fmaxf(__uint_as_float(g_minneg[i]), EPSF));
    float ls = fmaxf(dap - dan + MARGIN, 0.f);
    float dp = dap;
    float dn = dan;
    unsigned est = (unsigned)(g_protomin[i] & 0xffffffffull);
    float ac = (est == (unsigned)(i >> 3)) ? 1.f : 0.f;

    #pragma unroll
    for (int o = 16; o > 0; o >>= 1) {
        ls += __shfl_down_sync(0xffffffffu, ls, o);
        dp += __shfl_down_sync(0xffffffffu, dp, o);
        dn += __shfl_down_sync(0xffffffffu, dn, o);
        ac += __shfl_down_sync(0xffffffffu, ac, o);
    }
    int warp = tid >> 5, lane = tid & 31;
    if (lane == 0) { red[0][warp] = ls; red[1][warp] = dp; red[2][warp] = dn; red[3][warp] = ac; }
    __syncthreads();
    if (tid < 4) {
        float t = 0.f;
        #pragma unroll
        for (int w = 0; w < 8; w++) t += red[tid][w];
        // red[0]=loss->out[0], red[1]=dist_p->out[2], red[2]=dist_n->out[3], red[3]=acc->out[1]
        atomicAdd(&out[tid == 0 ? 0 : (tid == 3 ? 1 : tid + 1)], t * (1.0f / (float)N_TOT));
    }
}

// ---------------- launch ----------------------------------------------------
extern "C" void kernel_launch(void* const* d_in, const int* in_sizes, int n_in,
                              void* d_out, int out_size) {
    const float* x = (const float*)d_in[0];
    if (n_in > 1 && in_sizes[0] != N_TOT * DIMS) x = (const float*)d_in[1];
    float* out = (float*)d_out;

    cudaFuncSetAttribute(mma_gemm_kernel,
                         cudaFuncAttributeMaxDynamicSharedMemorySize, DSMEM);

    prep_kernel<<<NW, 256>>>(x, out);

    float* protos;
    cudaGetSymbolAddress((void**)&protos, g_protos);

    mma_gemm_kernel<<<TRI_BLKS + 256, 256, DSMEM>>>(x, protos);

    finalize_kernel<<<32, 256>>>(out);
}

// round 17
// speedup vs baseline: 1.5802x; 1.5802x over previous
#include <cuda_runtime.h>
#include <cstdint>

#define N_TOT 8192
#define DIMS  512
#define NI    8
#define NW    1024          // N_TOT / NI
#define MARGIN 0.3f
#define EPSF   1e-12f

typedef unsigned int u32;
typedef unsigned long long u64;

// ---------------- scratch (static device globals; no allocation) ------------
__device__ float g_sq[N_TOT];
__device__ float g_protos[NW * DIMS];
__device__ float g_psq[NW];
__device__ float g_distap[N_TOT];
__device__ u32   g_minneg[N_TOT];     // float-bits of min neg d2
__device__ u64   g_protomin[N_TOT];   // (d2bits<<32)|class

// ---------------- per-class prep (fp32-exact) + init -------------------------
// R15-proven: LDS.128 dots, psq derived from dot matrix (13.1 us measured).
__global__ void prep_kernel(const float* __restrict__ x, float* __restrict__ out) {
    __shared__ float xs[NI][DIMS + 4];
    __shared__ float dots[NI][NI];
    const int cls = blockIdx.x;
    const int tid = threadIdx.x;
    const float* base = x + (size_t)cls * NI * DIMS;

    if (cls == 0 && tid < 4) out[tid] = 0.f;   // zero output accumulators

    if (tid < NI) {                            // fused init
        g_minneg[cls * NI + tid]   = 0x7f800000u;
        g_protomin[cls * NI + tid] = 0xFFFFFFFFFFFFFFFFull;
    }

    {
        const float4* src = (const float4*)base;
        #pragma unroll
        for (int i = 0; i < 4; i++) {
            int k4 = tid + i * 256;            // 0..1023
            int r  = k4 >> 7;                  // 0..7
            int c4 = k4 & 127;
            *(float4*)&xs[r][c4 * 4] = src[k4];
        }
    }
    __syncthreads();

    // prototype (psq derived from dots below)
    for (int d = tid; d < DIMS; d += 256) {
        float s = 0.f;
        #pragma unroll
        for (int r = 0; r < NI; r++) s += xs[r][d];
        g_protos[cls * DIMS + d] = s * (1.0f / NI);
    }

    // 8x8 dots: one thread per pair, LDS.128 reads, 4 ILP accumulators
    if (tid < NI * NI) {
        int a = tid >> 3, b = tid & 7;
        const float4* ra = (const float4*)xs[a];
        const float4* rb = (const float4*)xs[b];
        float d0 = 0.f, d1 = 0.f, d2 = 0.f, d3 = 0.f;
        #pragma unroll 8
        for (int k4 = 0; k4 < DIMS / 4; k4++) {
            float4 va = ra[k4], vb = rb[k4];
            d0 = fmaf(va.x, vb.x, d0);
            d1 = fmaf(va.y, vb.y, d1);
            d2 = fmaf(va.z, vb.z, d2);
            d3 = fmaf(va.w, vb.w, d3);
        }
        float dot = (d0 + d1) + (d2 + d3);
        dots[a][b] = dot;
        if (a == b) g_sq[cls * NI + a] = dot;
    }
    __syncthreads();

    if (tid == 0) {
        // ||proto||^2 = (1/64) * sum_{a,b} x_a . x_b
        float s = 0.f;
        #pragma unroll
        for (int a = 0; a < NI; a++)
            #pragma unroll
            for (int b = 0; b < NI; b++) s += dots[a][b];
        g_psq[cls] = s * (1.0f / (NI * NI));
    }
    if (tid < NI) {
        int a = tid;
        float sqa = dots[a][a];
        float m = -1.f;
        #pragma unroll
        for (int b = 0; b < NI; b++) {
            float d2 = sqa + dots[b][b] - 2.f * dots[a][b];
            m = fmaxf(m, sqrtf(fmaxf(d2, EPSF)));
        }
        g_distap[cls * NI + a] = m;
    }
}

// ---------------- mma.sync tf32 helpers --------------------------------------
__device__ __forceinline__ void mma_tf32(float d[4], const u32 a[4], const u32 b[2]) {
    asm volatile(
        "mma.sync.aligned.m16n8k8.row.col.f32.tf32.tf32.f32 "
        "{%0,%1,%2,%3}, {%4,%5,%6,%7}, {%8,%9}, {%0,%1,%2,%3};"
        : "+f"(d[0]), "+f"(d[1]), "+f"(d[2]), "+f"(d[3])
        : "r"(a[0]), "r"(a[1]), "r"(a[2]), "r"(a[3]), "r"(b[0]), "r"(b[1]));
}
__device__ __forceinline__ void cpa16(u32 dst, const float* src) {
    asm volatile("cp.async.ca.shared.global [%0], [%1], 16;" :: "r"(dst), "l"(src));
}
__device__ __forceinline__ void cp_commit() {
    asm volatile("cp.async.commit_group;" ::: "memory");
}

// ---------------- fused tf32 mma GEMM + mining, merged grid ------------------
// R13-proven mainloop: CTA tile 128x256, 8 warps x (64x64), K chunk 32,
// 3-stage cp.async, 1 barrier/chunk, single-buffered fragments.
// Blocks [0, 1056): wedge tiles of the self-Gram (row+col mining).
// Blocks [1056, 1312): proto GEMM tiles (64 row-blocks x 4 col-blocks).
#define TSTRIDE 36
#define A_ROWS  128
#define B_ROWS  256
#define A_F     (A_ROWS * TSTRIDE)
#define STAGE_F ((A_ROWS + B_ROWS) * TSTRIDE)  // 13824 floats
#define NSTAGE  3
#define NCHUNK  16                        // 512 / 32
#define TRI_BLKS 1056
#define DSMEM   (NSTAGE * STAGE_F * 4)    // 165888 bytes

__global__ __launch_bounds__(256)
void mma_gemm_kernel(const float* __restrict__ A, const float* __restrict__ P) {
    extern __shared__ float dsm[];

    const int tid  = threadIdx.x;
    const int wid  = tid >> 5;
    const int lane = tid & 31;
    const int g    = lane >> 2;
    const int tg   = lane & 3;
    const int rowOff = (wid >> 2) * 64;   // 0 or 64
    const int colOff = (wid & 3) * 64;    // 0,64,128,192

    // ---- decode block -> (mode, rowBase, colBase) ----
    int mode, bxr, byr;
    if ((int)blockIdx.x < TRI_BLKS) {
        mode = 0;
        int t = blockIdx.x;
        int q = (int)((65.0f - sqrtf(4225.0f - 4.0f * (float)t)) * 0.5f);
        if (q < 0) q = 0;
        while (64 * (q + 1) - (q + 1) * q <= t) ++q;
        while (64 * q - q * (q - 1) > t) --q;
        int rem = t - (64 * q - q * (q - 1));
        int cnt = 32 - q;
        int sub = rem >= cnt ? 1 : 0;
        byr = 2 * q + sub;
        bxr = q + (rem - sub * cnt);
    } else {
        mode = 1;
        int p = blockIdx.x - TRI_BLKS;    // 0..255
        byr = p >> 2;
        bxr = p & 3;
    }
    const int rowBase = byr * 128;
    const int colBase = bxr * 256;
    const float* __restrict__ Bp = mode ? P : A;

    auto load_stage = [&](int slot, int c) {
        float* base = dsm + slot * STAGE_F;
        const int k0 = c * 32;
        #pragma unroll
        for (int i = 0; i < 12; i++) {
            int f  = tid + i * 256;              // 0..3071
            int r  = f >> 3;                     // 0..383
            int kc = (f & 7) * 4;
            const float* src;
            float* dstp;
            if (r < A_ROWS) {
                src  = A + (size_t)(rowBase + r) * DIMS + k0 + kc;
                dstp = base + r * TSTRIDE + kc;
            } else {
                src  = Bp + (size_t)(colBase + (r - A_ROWS)) * DIMS + k0 + kc;
                dstp = base + A_F + (r - A_ROWS) * TSTRIDE + kc;
            }
            cpa16((u32)__cvta_generic_to_shared(dstp), src);
        }
    };

    float acc[4][8][4];
    #pragma unroll
    for (int mi = 0; mi < 4; mi++)
        #pragma unroll
        for (int nt = 0; nt < 8; nt++)
            #pragma unroll
            for (int q = 0; q < 4; q++) acc[mi][nt][q] = 0.f;

    load_stage(0, 0); cp_commit();
    load_stage(1, 1); cp_commit();

    for (int c = 0; c < NCHUNK; c++) {
        asm volatile("cp.async.wait_group 1;" ::: "memory");
        __syncthreads();
        if (c + 2 < NCHUNK) load_stage((c + 2) % NSTAGE, c + 2);
        cp_commit();

        const float* Asb = dsm + (c % NSTAGE) * STAGE_F;
        const float* Bsb = Asb + A_F;
        #pragma unroll
        for (int h = 0; h < 4; h++) {
            const int kc = h * 8 + tg;
            u32 afr[4][4];
            #pragma unroll
            for (int mi = 0; mi < 4; mi++) {
                const float* ap = Asb + (rowOff + mi * 16 + g) * TSTRIDE;
                afr[mi][0] = __float_as_uint(ap[kc]);
                afr[mi][1] = __float_as_uint(ap[8 * TSTRIDE + kc]);
                afr[mi][2] = __float_as_uint(ap[kc + 4]);
                afr[mi][3] = __float_as_uint(ap[8 * TSTRIDE + kc + 4]);
            }
            u32 bfr[8][2];
            #pragma unroll
            for (int nt = 0; nt < 8; nt++) {
                const float* bp = Bsb + (colOff + nt * 8 + g) * TSTRIDE;
                bfr[nt][0] = __float_as_uint(bp[kc]);
                bfr[nt][1] = __float_as_uint(bp[kc + 4]);
            }
            #pragma unroll
            for (int mi = 0; mi < 4; mi++)
                #pragma unroll
                for (int nt = 0; nt < 8; nt++)
                    mma_tf32(acc[mi][nt], afr[mi], bfr[nt]);
        }
    }
    asm volatile("cp.async.wait_group 0;" ::: "memory");
    __syncthreads();

    // ---------------- epilogue: mine (arrays aliased into dsm) ----------------
    float* s_sqc  = dsm;                   // 256 f32
    u32*   s_rmin = (u32*)(dsm + 256);     // 128 u32
    u32*   s_cmin = (u32*)(dsm + 384);     // 256 u32
    u64*   s_key  = (u64*)(dsm + 640);     // 128 u64

    const float INF = __int_as_float(0x7f800000);
    s_sqc[tid]  = (mode == 0) ? g_sq[colBase + tid] : g_psq[colBase + tid];
    s_cmin[tid] = 0x7f800000u;
    if (tid < 128) {
        s_rmin[tid] = 0x7f800000u;
        s_key[tid]  = 0xFFFFFFFFFFFFFFFFull;
    }
    __syncthreads();

    const bool straddle = (mode == 0) && ((byr >> 1) == bxr);

    if (mode == 0) {
        float cm[8][2];
        #pragma unroll
        for (int nt = 0; nt < 8; nt++) { cm[nt][0] = INF; cm[nt][1] = INF; }

        #pragma unroll
        for (int mi = 0; mi < 4; mi++) {
            #pragma unroll
            for (int half = 0; half < 2; half++) {
                const int r = rowOff + mi * 16 + g + half * 8;
                const float sqr = g_sq[rowBase + r];
                const int rcls = (rowBase + r) >> 3;
                float rmin = INF;
                #pragma unroll
                for (int nt = 0; nt < 8; nt++) {
                    #pragma unroll
                    for (int cc = 0; cc < 2; cc++) {
                        const int col = colOff + nt * 8 + 2 * tg + cc;
                        float dot = acc[mi][nt][half * 2 + cc];
                        float d2 = fmaxf(sqr + s_sqc[col] - 2.f * dot, 0.f);
                        if (straddle && (((colBase + col) >> 3) == rcls)) d2 = INF;
                        rmin = fminf(rmin, d2);
                        cm[nt][cc] = fminf(cm[nt][cc], d2);
                    }
                }
                atomicMin(&s_rmin[r], __float_as_uint(rmin));
            }
        }
        #pragma unroll
        for (int off = 4; off < 32; off <<= 1)
            #pragma unroll
            for (int nt = 0; nt < 8; nt++) {
                cm[nt][0] = fminf(cm[nt][0], __shfl_xor_sync(0xffffffffu, cm[nt][0], off));
                cm[nt][1] = fminf(cm[nt][1], __shfl_xor_sync(0xffffffffu, cm[nt][1], off));
            }
        if (g == 0) {
            #pragma unroll
            for (int nt = 0; nt < 8; nt++) {
                atomicMin(&s_cmin[colOff + nt * 8 + 2 * tg],     __float_as_uint(cm[nt][0]));
                atomicMin(&s_cmin[colOff + nt * 8 + 2 * tg + 1], __float_as_uint(cm[nt][1]));
            }
        }
        __syncthreads();
        if (tid < 128) atomicMin(&g_minneg[rowBase + tid], s_rmin[tid]);
        atomicMin(&g_minneg[colBase + tid], s_cmin[tid]);
    } else {
        #pragma unroll
        for (int mi = 0; mi < 4; mi++) {
            #pragma unroll
            for (int half = 0; half < 2; half++) {
                const int r = rowOff + mi * 16 + g + half * 8;
                const float sqr = g_sq[rowBase + r];
                u64 kmin = 0xFFFFFFFFFFFFFFFFull;
                #pragma unroll
                for (int nt = 0; nt < 8; nt++) {
                    #pragma unroll
                    for (int cc = 0; cc < 2; cc++) {
                        const int col = colOff + nt * 8 + 2 * tg + cc;
                        float dot = acc[mi][nt][half * 2 + cc];
                        float d2 = fmaxf(sqr + s_sqc[col] - 2.f * dot, 0.f);
                        u64 key = ((u64)__float_as_uint(d2) << 32) | (u32)(colBase + col);
                        kmin = key < kmin ? key : kmin;
                    }
                }
                #pragma unroll
                for (int off = 1; off < 4; off <<= 1) {
                    u64 o = __shfl_xor_sync(0xffffffffu, kmin, off);
                    kmin = o < kmin ? o : kmin;
                }
                if (tg == 0) atomicMin(&s_key[r], kmin);
            }
        }
        __syncthreads();
        if (tid < 128) atomicMin(&g_protomin[rowBase + tid], s_key[tid]);
    }
}

// ---------------- finalize: 32 blocks, atomic accumulate ---------------------
__global__ void finalize_kernel(float* __restrict__ out) {
    __shared__ float red[4][8];
    const int i = blockIdx.x * 256 + threadIdx.x;
    const int tid = threadIdx.x;

    float dap = g_distap[i];
    float dan = sqrtf(fmaxf(__uint_as_float(g_minneg[i]), EPSF));
    float ls = fmaxf(dap - dan + MARGIN, 0.f);
    float dp = dap;
    float dn = dan;
    unsigned est = (unsigned)(g_protomin[i] & 0xffffffffull);
    float ac = (est == (unsigned)(i >> 3)) ? 1.f : 0.f;

    #pragma unroll
    for (int o = 16; o > 0; o >>= 1) {
        ls += __shfl_down_sync(0xffffffffu, ls, o);
        dp += __shfl_down_sync(0xffffffffu, dp, o);
        dn += __shfl_down_sync(0xffffffffu, dn, o);
        ac += __shfl_down_sync(0xffffffffu, ac, o);
    }
    int warp = tid >> 5, lane = tid & 31;
    if (lane == 0) { red[0][warp] = ls; red[1][warp] = dp; red[2][warp] = dn; red[3][warp] = ac; }
    __syncthreads();
    if (tid < 4) {
        float t = 0.f;
        #pragma unroll
        for (int w = 0; w < 8; w++) t += red[tid][w];
        // red[0]=loss->out[0], red[1]=dist_p->out[2], red[2]=dist_n->out[3], red[3]=acc->out[1]
        atomicAdd(&out[tid == 0 ? 0 : (tid == 3 ? 1 : tid + 1)], t * (1.0f / (float)N_TOT));
    }
}

// ---------------- launch ----------------------------------------------------
extern "C" void kernel_launch(void* const* d_in, const int* in_sizes, int n_in,
                              void* d_out, int out_size) {
    const float* x = (const float*)d_in[0];
    if (n_in > 1 && in_sizes[0] != N_TOT * DIMS) x = (const float*)d_in[1];
    float* out = (float*)d_out;

    cudaFuncSetAttribute(mma_gemm_kernel,
                         cudaFuncAttributeMaxDynamicSharedMemorySize, DSMEM);

    prep_kernel<<<NW, 256>>>(x, out);

    float* protos;
    cudaGetSymbolAddress((void**)&protos, g_protos);

    mma_gemm_kernel<<<TRI_BLKS + 256, 256, DSMEM>>>(x, protos);

    finalize_kernel<<<32, 256>>>(out);
}